// round 2
// baseline (speedup 1.0000x reference)
#include <cuda_runtime.h>
#include <cstdint>

// Problem shape (fixed by the dataset):
//   E=8192 envs, A=128 agents/env, K=512 passengers/env, P=E*K rows x 11 cols.
// Inputs (metadata order): passengers f32[P,11], accepts bool->i32[E,A],
//   picks bool->i32[E,A], targets i32[E,A], vectors f32[E,A,4], timesteps i32[E].
// Output f32[P,11].

#define NENV   8192
#define NAG    128
#define NPASS  512
#define NTHR   256
#define ROWF   11
#define VEC4S  ((NPASS * ROWF) / 4)   // 1408 float4 per env chunk (22528 B, 16B aligned)

__global__ __launch_bounds__(NTHR, 8)
void pst_kernel(const float* __restrict__ passengers,
                const unsigned int* __restrict__ accepts,   // bool widened to 32-bit
                const unsigned int* __restrict__ picks,     // bool widened to 32-bit
                const int* __restrict__ targets,
                const float* __restrict__ vectors,
                const int* __restrict__ timesteps,
                float* __restrict__ out)
{
    const int e   = blockIdx.x;
    const int tid = threadIdx.x;

    __shared__ int              cnt[NPASS];        // per-local-passenger accept count
    __shared__ short            acc_agent[NPASS];  // surviving accepting agent, -1 = none
    __shared__ unsigned char    picked[NPASS];
    __shared__ unsigned long long red[NTHR];       // (dist_bits<<32)|agent for argmin
    __shared__ float            ts_s;

    // ---- init per-passenger smem ----
    for (int i = tid; i < NPASS; i += NTHR) { cnt[i] = 0; acc_agent[i] = -1; picked[i] = 0; }
    if (tid == 0) ts_s = (float)__ldg(&timesteps[e]);

    const float INF = __int_as_float(0x7f800000);

    float d   = INF;
    int   lt  = 0;
    bool  acc = false, pk = false;
    if (tid < NAG) {
        float4 v = reinterpret_cast<const float4*>(vectors)[(size_t)e * NAG + tid];
        float dx = v.x - v.z, dy = v.y - v.w;
        d = sqrtf(dx * dx + dy * dy);
        if (v.x == -100.0f && v.y == -100.0f && v.z == -100.0f && v.w == -100.0f) d = INF;
        lt  = __ldg(&targets[e * NAG + tid]) - e * NPASS;   // local passenger index [0,512)
        // nonzero test works whether bool was widened to int32 (1) or float32 (0x3F800000)
        acc = (accepts[e * NAG + tid] != 0u);
        pk  = (picks  [e * NAG + tid] != 0u);
    }
    __syncthreads();

    // ---- target multiplicity among accepting agents ----
    if (acc) atomicAdd(&cnt[lt], 1);
    __syncthreads();

    // ---- duplicate mask + per-env argmin over where(dup, d, inf) ----
    // JAX argmin semantics: first index achieving the min; all-inf row -> index 0.
    // Key ((bits of nonneg float) << 32) | index is monotone in value, ties -> lowest idx.
    bool dup = acc && (cnt[lt] > 1);
    unsigned long long key;
    if (tid < NAG) {
        float dv = dup ? d : INF;
        key = ((unsigned long long)__float_as_uint(dv) << 32) | (unsigned)tid;
    } else {
        key = ~0ull;
    }
    red[tid] = key;
    __syncthreads();
    #pragma unroll
    for (int s = NTHR / 2; s > 0; s >>= 1) {
        if (tid < s) { unsigned long long o = red[tid + s]; if (o < red[tid]) red[tid] = o; }
        __syncthreads();
    }
    const int keep = (int)(red[0] & 0xffffffffu);

    // ---- surviving accepts + zero-distance picks -> per-passenger flags ----
    // (While-loop converges in exactly one body call: the argmin agent keeps its
    //  target; every other duplicate agent is removed, leaving no duplicates.)
    if (tid < NAG) {
        bool surviving = acc && !(dup && tid != keep);
        if (surviving) acc_agent[lt] = (short)tid;            // unique writer post-resolution
        if (pk && d < 1e-6f) picked[lt] = 1;                  // racing writers store same value
    }
    __syncthreads();

    // ---- stream-copy this env's 512x11 chunk, patching cols 6/7/9/10 ----
    const float4* __restrict__ src = reinterpret_cast<const float4*>(passengers) + (size_t)e * VEC4S;
    float4*       __restrict__ dst = reinterpret_cast<float4*>(out) + (size_t)e * VEC4S;
    const float ts = ts_s;

    #pragma unroll 2
    for (int i = tid; i < VEC4S; i += NTHR) {
        float4 v = src[i];
        float* vp = &v.x;
        const int base = i * 4;
        #pragma unroll
        for (int j = 0; j < 4; j++) {
            const int lf  = base + j;
            const int row = lf / ROWF;          // const divide -> mul/shift
            const int col = lf - row * ROWF;
            const int a   = acc_agent[row];
            const unsigned char pq = picked[row];
            if (a >= 0 || pq) {
                float val = vp[j];
                if      (col == 6)  val = pq ? 2.0f : (a >= 0 ? 1.0f : val);
                else if (col == 7)  { if (a >= 0) val = (float)a; }
                else if (col == 9)  { if (a >= 0) val = ts; }
                else if (col == 10) { if (pq)     val = ts; }
                vp[j] = val;
            }
        }
        dst[i] = v;
    }
}

extern "C" void kernel_launch(void* const* d_in, const int* in_sizes, int n_in,
                              void* d_out, int out_size)
{
    const float*        passengers = (const float*)d_in[0];
    const unsigned int* accepts    = (const unsigned int*)d_in[1];
    const unsigned int* picks      = (const unsigned int*)d_in[2];
    const int*          targets    = (const int*)d_in[3];
    const float*        vectors    = (const float*)d_in[4];
    const int*          timesteps  = (const int*)d_in[5];
    float*              out        = (float*)d_out;

    pst_kernel<<<NENV, NTHR>>>(passengers, accepts, picks, targets, vectors, timesteps, out);
}

// round 3
// speedup vs baseline: 1.3739x; 1.3739x over previous
#include <cuda_runtime.h>
#include <cstdint>

// E=8192 envs, A=128 agents/env, K=512 passengers/env, P=E*K rows x 11 f32 cols.
// Inputs: passengers f32[P,11], accepts/picks bool->32bit [E,A], targets i32[E,A],
//         vectors f32[E,A,4], timesteps i32[E]. Output f32[P,11].

#define NENV   8192
#define NAG    128
#define NPASS  512
#define NTHR   256
#define ROWF   11
#define VEC4S  ((NPASS * ROWF) / 4)   // 1408 float4 per env chunk (22528 B)

__global__ __launch_bounds__(NTHR, 6)
void pst_kernel(const float* __restrict__ passengers,
                const unsigned int* __restrict__ accepts,
                const unsigned int* __restrict__ picks,
                const int* __restrict__ targets,
                const float* __restrict__ vectors,
                const int* __restrict__ timesteps,
                float* __restrict__ out)
{
    const int e   = blockIdx.x;
    const int tid = threadIdx.x;

    __shared__ int                cnt[NPASS];        // accept multiplicity per local passenger
    __shared__ short              acc_agent[NPASS];  // surviving accepting agent, -1 = none
    __shared__ unsigned char      picked[NPASS];
    __shared__ unsigned long long red[NTHR];         // (dist_bits<<32)|agent argmin key
    __shared__ float              ts_s;

    // ================= phase 0: kick off the pure stream copy loads =================
    // Front-batch the bulk loads so HBM traffic is in flight while the
    // conflict-resolution logic below runs. 1408 = 5*256 + 128.
    const float4* __restrict__ src = reinterpret_cast<const float4*>(passengers) + (size_t)e * VEC4S;
    float4*       __restrict__ dst = reinterpret_cast<float4*>(out) + (size_t)e * VEC4S;

    float4 c0 = src[tid];
    float4 c1 = src[tid + 1 * NTHR];
    float4 c2 = src[tid + 2 * NTHR];
    float4 c3 = src[tid + 3 * NTHR];
    float4 c4 = src[tid + 4 * NTHR];
    float4 c5;
    if (tid < VEC4S - 5 * NTHR) c5 = src[tid + 5 * NTHR];

    // ================= phase 1: per-agent state =================
    for (int i = tid; i < NPASS; i += NTHR) { cnt[i] = 0; acc_agent[i] = -1; picked[i] = 0; }
    if (tid == 0) ts_s = (float)__ldg(&timesteps[e]);

    const float INF = __int_as_float(0x7f800000);
    float d  = INF;
    int   lt = 0;
    bool  acc = false, pk = false;
    if (tid < NAG) {
        float4 v = reinterpret_cast<const float4*>(vectors)[(size_t)e * NAG + tid];
        float dx = v.x - v.z, dy = v.y - v.w;
        d = sqrtf(dx * dx + dy * dy);
        if (v.x == -100.0f && v.y == -100.0f && v.z == -100.0f && v.w == -100.0f) d = INF;
        lt  = __ldg(&targets[e * NAG + tid]) - e * NPASS;       // local idx in [0,512)
        acc = (accepts[e * NAG + tid] != 0u);                   // robust to i32/f32 widening
        pk  = (picks  [e * NAG + tid] != 0u);
    }
    __syncthreads();

    // accept multiplicity
    if (acc) atomicAdd(&cnt[lt], 1);
    __syncthreads();

    // duplicate mask + per-env argmin over where(dup, d, inf).
    // JAX argmin: first index achieving min; all-inf -> index 0. Key is monotone,
    // ties resolve to lowest agent index. While-loop converges in one body call.
    bool dup = acc && (cnt[lt] > 1);
    unsigned long long key = ~0ull;
    if (tid < NAG)
        key = ((unsigned long long)__float_as_uint(dup ? d : INF) << 32) | (unsigned)tid;
    red[tid] = key;
    __syncthreads();
    #pragma unroll
    for (int s = NTHR / 2; s > 0; s >>= 1) {
        if (tid < s) { unsigned long long o = red[tid + s]; if (o < red[tid]) red[tid] = o; }
        __syncthreads();
    }
    const int keep = (int)(red[0] & 0xffffffffu);

    if (tid < NAG) {
        bool surviving = acc && !(dup && tid != keep);
        if (surviving) acc_agent[lt] = (short)tid;   // unique writer after resolution
        if (pk && d < 1e-6f) picked[lt] = 1;         // racing writers store identical value
    }

    // ================= phase 2: store the bulk copy =================
    dst[tid]            = c0;
    dst[tid + 1 * NTHR] = c1;
    dst[tid + 2 * NTHR] = c2;
    dst[tid + 3 * NTHR] = c3;
    dst[tid + 4 * NTHR] = c4;
    if (tid < VEC4S - 5 * NTHR) dst[tid + 5 * NTHR] = c5;

    // order: all bulk stores (and flag smem writes) before sparse patch overwrites
    __syncthreads();

    // ================= phase 3: sparse per-row patches =================
    const float ts = ts_s;
    float* __restrict__ outf = reinterpret_cast<float*>(dst);
    #pragma unroll
    for (int r = tid; r < NPASS; r += NTHR) {
        const int           a  = acc_agent[r];
        const unsigned char pq = picked[r];
        if ((a >= 0) | pq) {
            float* row = outf + r * ROWF;
            row[6] = pq ? 2.0f : 1.0f;              // a>=0 guaranteed when !pq here
            if (a >= 0) { row[7] = (float)a; row[9] = ts; }
            if (pq)     { row[10] = ts; }
        }
    }
}

extern "C" void kernel_launch(void* const* d_in, const int* in_sizes, int n_in,
                              void* d_out, int out_size)
{
    const float*        passengers = (const float*)d_in[0];
    const unsigned int* accepts    = (const unsigned int*)d_in[1];
    const unsigned int* picks      = (const unsigned int*)d_in[2];
    const int*          targets    = (const int*)d_in[3];
    const float*        vectors    = (const float*)d_in[4];
    const int*          timesteps  = (const int*)d_in[5];
    float*              out        = (float*)d_out;

    pst_kernel<<<NENV, NTHR>>>(passengers, accepts, picks, targets, vectors, timesteps, out);
}

// round 4
// speedup vs baseline: 1.4632x; 1.0650x over previous
#include <cuda_runtime.h>
#include <cstdint>

// E=8192 envs, A=128 agents/env, K=512 passengers/env, P=E*K rows x 11 f32 cols.
// Inputs: passengers f32[P,11], accepts/picks bool->32bit [E,A], targets i32[E,A],
//         vectors f32[E,A,4], timesteps i32[E]. Output f32[P,11].

#define NENV   8192
#define NAG    128
#define NPASS  512
#define NTHR   256
#define ROWF   11
#define VEC4S  ((NPASS * ROWF) / 4)   // 1408 float4 per env chunk (22528 B)

__global__ __launch_bounds__(NTHR, 6)
void pst_kernel(const float* __restrict__ passengers,
                const unsigned int* __restrict__ accepts,
                const unsigned int* __restrict__ picks,
                const int* __restrict__ targets,
                const float* __restrict__ vectors,
                const int* __restrict__ timesteps,
                float* __restrict__ out)
{
    const int e   = blockIdx.x;
    const int tid = threadIdx.x;

    __shared__ int                cnt[NPASS];      // accept multiplicity per local passenger
    __shared__ unsigned char      picked[NPASS];   // zero-dist pick landed on this row
    __shared__ unsigned long long minkey;          // (dist_bits<<32)|agent argmin
    __shared__ float              ts_s;

    // ---------- phase 0: front-batch the streaming loads (HBM in flight early) ----------
    const float4* __restrict__ src = reinterpret_cast<const float4*>(passengers) + (size_t)e * VEC4S;
    float4*       __restrict__ dst = reinterpret_cast<float4*>(out) + (size_t)e * VEC4S;

    // small per-agent loads first so they're not queued behind 24KB of stream
    const float INF = __int_as_float(0x7f800000);
    float d  = INF;
    int   lt = 0;
    bool  acc = false, pk = false;
    float4 av;
    if (tid < NAG) {
        av  = reinterpret_cast<const float4*>(vectors)[(size_t)e * NAG + tid];
        lt  = __ldg(&targets[e * NAG + tid]) - e * NPASS;       // local idx in [0,512)
        acc = (accepts[e * NAG + tid] != 0u);                   // robust to i32/f32 widening
        pk  = (picks  [e * NAG + tid] != 0u);
    }

    float4 c0 = src[tid];
    float4 c1 = src[tid + 1 * NTHR];
    float4 c2 = src[tid + 2 * NTHR];
    float4 c3 = src[tid + 3 * NTHR];
    float4 c4 = src[tid + 4 * NTHR];
    float4 c5;
    if (tid < VEC4S - 5 * NTHR) c5 = src[tid + 5 * NTHR];

    // ---------- phase 1: flag resolution (4 barriers total) ----------
    for (int i = tid; i < NPASS; i += NTHR) { cnt[i] = 0; picked[i] = 0; }
    if (tid == 0) { ts_s = (float)__ldg(&timesteps[e]); minkey = ~0ull; }

    if (tid < NAG) {
        float dx = av.x - av.z, dy = av.y - av.w;
        d = sqrtf(dx * dx + dy * dy);
        if (av.x == -100.0f && av.y == -100.0f && av.z == -100.0f && av.w == -100.0f) d = INF;
    }
    __syncthreads();                                            // B1: smem init done

    if (acc) atomicAdd(&cnt[lt], 1);
    if (tid < NAG && pk && d < 1e-6f) picked[lt] = 1;           // independent of dedup
    __syncthreads();                                            // B2: counts + picked visible

    // dup mask + per-env argmin over where(dup, d, inf).
    // JAX argmin: first index achieving min; all-inf -> index 0. Key bits are
    // monotone in the (nonneg) distance; ties resolve to lowest agent index.
    // The reference while-loop converges in exactly one body call.
    bool dup = acc && (cnt[lt] > 1);
    if (tid < NAG) {
        unsigned long long key =
            ((unsigned long long)__float_as_uint(dup ? d : INF) << 32) | (unsigned)tid;
        #pragma unroll
        for (int s = 16; s > 0; s >>= 1) {
            unsigned long long o = __shfl_down_sync(0xffffffffu, key, s);
            if (o < key) key = o;
        }
        if ((tid & 31) == 0) atomicMin(&minkey, key);
    }
    __syncthreads();                                            // B3: argmin resolved
    const int keep = (int)(minkey & 0xffffffffu);

    // ---------- phase 2: bulk store ----------
    dst[tid]            = c0;
    dst[tid + 1 * NTHR] = c1;
    dst[tid + 2 * NTHR] = c2;
    dst[tid + 3 * NTHR] = c3;
    dst[tid + 4 * NTHR] = c4;
    if (tid < VEC4S - 5 * NTHR) dst[tid + 5 * NTHR] = c5;
    __syncthreads();                                            // B4: bulk before patches

    // ---------- phase 3: agent-driven sparse patches ----------
    // After dedup at most one surviving accept agent per row -> unique writer for
    // cols 7/9 (and 6 when no pick). Racing pick writers store identical values.
    if (tid < NAG) {
        const float ts = ts_s;
        float* row = reinterpret_cast<float*>(dst) + lt * ROWF;
        bool surviving = acc && !(dup && tid != keep);
        if (surviving) {
            row[7] = (float)tid;
            row[9] = ts;
            if (!picked[lt]) row[6] = 1.0f;
        }
        if (pk && d < 1e-6f) {
            row[6]  = 2.0f;
            row[10] = ts;
        }
    }
}

extern "C" void kernel_launch(void* const* d_in, const int* in_sizes, int n_in,
                              void* d_out, int out_size)
{
    const float*        passengers = (const float*)d_in[0];
    const unsigned int* accepts    = (const unsigned int*)d_in[1];
    const unsigned int* picks      = (const unsigned int*)d_in[2];
    const int*          targets    = (const int*)d_in[3];
    const float*        vectors    = (const float*)d_in[4];
    const int*          timesteps  = (const int*)d_in[5];
    float*              out        = (float*)d_out;

    pst_kernel<<<NENV, NTHR>>>(passengers, accepts, picks, targets, vectors, timesteps, out);
}